// round 7
// baseline (speedup 1.0000x reference)
#include <cuda_runtime.h>
#include <cstdint>

#define V 12288
#define CIN 16
#define COUT 32
#define KORD 5
#define NKS 3               // k-slices per pass  -> 96*3 = 288 CTAs = 1 wave
#define KSL (V / NKS)       // 4096
#define CHK 64              // u per chunk
#define NCHK (KSL / CHK)    // 64
#define CV (CIN * V)
#define RS 72               // smem row stride in bf16 elements (bank-conflict-free frags)
#define RSB (RS * 2)        // 144 bytes

// fp32 scratch: T1..T4 and per-kslice partials
__device__ float g_T[4][CV];
__device__ float g_part[NKS][CV];

// smem byte offsets
#define AH_OFF 0
#define AL_OFF (128 * RSB)            // 18432
#define BH_OFF (2 * 128 * RSB)        // 36864
#define BL_OFF (BH_OFF + 16 * RSB)    // 39168
#define SMEM_BYTES (BL_OFF + 16 * RSB)

__device__ __forceinline__ uint32_t lds32(uint32_t a) {
    uint32_t v;
    asm volatile("ld.shared.b32 %0, [%1];" : "=r"(v) : "r"(a));
    return v;
}
__device__ __forceinline__ void sts64(uint32_t a, uint32_t w0, uint32_t w1) {
    asm volatile("st.shared.v2.b32 [%0], {%1,%2};" :: "r"(a), "r"(w0), "r"(w1) : "memory");
}

// split fp32 x4 -> bf16 hi (truncate) + bf16 lo (residual, RN); store 8B to each tile
__device__ __forceinline__ void split_sts(float4 f, uint32_t ah, uint32_t al) {
    uint32_t b0 = __float_as_uint(f.x), b1 = __float_as_uint(f.y);
    uint32_t b2 = __float_as_uint(f.z), b3 = __float_as_uint(f.w);
    uint32_t h0 = __byte_perm(b0, b1, 0x7632);
    uint32_t h1 = __byte_perm(b2, b3, 0x7632);
    float l0 = f.x - __uint_as_float(b0 & 0xFFFF0000u);
    float l1 = f.y - __uint_as_float(b1 & 0xFFFF0000u);
    float l2 = f.z - __uint_as_float(b2 & 0xFFFF0000u);
    float l3 = f.w - __uint_as_float(b3 & 0xFFFF0000u);
    uint32_t w0, w1;
    asm("cvt.rn.bf16x2.f32 %0, %1, %2;" : "=r"(w0) : "f"(l1), "f"(l0));
    asm("cvt.rn.bf16x2.f32 %0, %1, %2;" : "=r"(w1) : "f"(l3), "f"(l2));
    sts64(ah, h0, h1);
    sts64(al, w0, w1);
}

__device__ __forceinline__ void mma_bf16(float* c, uint32_t a0, uint32_t a1,
                                         uint32_t a2, uint32_t a3,
                                         uint32_t b0, uint32_t b1) {
    asm volatile("mma.sync.aligned.m16n8k16.row.col.f32.bf16.bf16.f32 "
                 "{%0,%1,%2,%3}, {%4,%5,%6,%7}, {%8,%9}, {%0,%1,%2,%3};"
                 : "+f"(c[0]), "+f"(c[1]), "+f"(c[2]), "+f"(c[3])
                 : "r"(a0), "r"(a1), "r"(a2), "r"(a3), "r"(b0), "r"(b1));
}

// ---------------- pass kernel ----------------
// g_part[ks][ch][v] = sum_{u in kslice} B[ch][u] * L[v][u]
// L fp32 [V][V]; B fp32 [CIN][V]. In-kernel bf16 hi/lo split, 3 HMMA products.
__global__ __launch_bounds__(256, 2)
void cheb_pass_mma(const float* __restrict__ L, const float* __restrict__ B)
{
    __shared__ __align__(16) uint8_t smem[SMEM_BYTES];
    const uint32_t sb = (uint32_t)__cvta_generic_to_shared(smem);

    const int t    = threadIdx.x;
    const int warp = t >> 5;
    const int lane = t & 31;
    const int g    = lane >> 2;      // group id (0..7)
    const int tc   = lane & 3;       // thread in group
    const int vt   = blockIdx.x % 96;
    const int ks   = blockIdx.x / 96;
    const int ub   = ks * KSL;

    // A staging: thread t -> L row (t>>1), k-half (t&1)*32 floats, 8 float4 each
    const int arow  = t >> 1;
    const int ahalf = t & 1;
    const float* Ag = L + (size_t)(vt * 128 + arow) * V + ub + ahalf * 32;
    const uint32_t a_sts = sb + (uint32_t)(arow * RSB + ahalf * 64);
    // B staging: thread t -> T row (t>>4), float4 quad (t&15)
    const float* Bg = B + (size_t)(t >> 4) * V + ub + (t & 15) * 4;
    const uint32_t b_sts = sb + (uint32_t)((t >> 4) * RSB + (t & 15) * 8);

    // fragment LDS base addresses (per warp: rows vw..vw+15)
    const int vw = warp * 16;
    const uint32_t a_frag = sb + (uint32_t)((vw + g) * RSB + tc * 4);
    const uint32_t b_frag = sb + (uint32_t)(g * RSB + tc * 4);

    float c0[4] = {0.f, 0.f, 0.f, 0.f};   // channels 0..7
    float c1[4] = {0.f, 0.f, 0.f, 0.f};   // channels 8..15

    float4 la[8];
    float4 lb;
#pragma unroll
    for (int j = 0; j < 8; j++) la[j] = __ldcs((const float4*)(Ag + j * 4));
    lb = __ldg((const float4*)(Bg));

#pragma unroll 1
    for (int c = 0; c < NCHK; c++) {
        if (c) __syncthreads();       // previous compute done before overwrite
        // stage current chunk (split fp32 -> bf16 hi/lo)
#pragma unroll
        for (int j = 0; j < 8; j++)
            split_sts(la[j], a_sts + AH_OFF + j * 8, a_sts + AL_OFF + j * 8);
        split_sts(lb, b_sts + BH_OFF, b_sts + BL_OFF);
        __syncthreads();

        // prefetch next chunk into regs (overlaps with compute below)
        if (c + 1 < NCHK) {
            const int off = (c + 1) * CHK;
#pragma unroll
            for (int j = 0; j < 8; j++)
                la[j] = __ldcs((const float4*)(Ag + off + j * 4));
            lb = __ldg((const float4*)(Bg + off));
        }

        // compute: 4 k-steps x (2 n-tiles x 3 products)
#pragma unroll
        for (int s = 0; s < 4; s++) {
            const uint32_t ao = a_frag + s * 32;
            const uint32_t bo = b_frag + s * 32;
            uint32_t ah0 = lds32(ao + AH_OFF);
            uint32_t ah1 = lds32(ao + AH_OFF + 8 * RSB);
            uint32_t ah2 = lds32(ao + AH_OFF + 16);
            uint32_t ah3 = lds32(ao + AH_OFF + 8 * RSB + 16);
            uint32_t al0 = lds32(ao + AL_OFF);
            uint32_t al1 = lds32(ao + AL_OFF + 8 * RSB);
            uint32_t al2 = lds32(ao + AL_OFF + 16);
            uint32_t al3 = lds32(ao + AL_OFF + 8 * RSB + 16);

            uint32_t bh0 = lds32(bo + BH_OFF);
            uint32_t bh1 = lds32(bo + BH_OFF + 16);
            uint32_t bl0 = lds32(bo + BL_OFF);
            uint32_t bl1 = lds32(bo + BL_OFF + 16);
            mma_bf16(c0, ah0, ah1, ah2, ah3, bh0, bh1);
            mma_bf16(c0, ah0, ah1, ah2, ah3, bl0, bl1);
            mma_bf16(c0, al0, al1, al2, al3, bh0, bh1);

            uint32_t ch0 = lds32(bo + BH_OFF + 8 * RSB);
            uint32_t ch1 = lds32(bo + BH_OFF + 8 * RSB + 16);
            uint32_t cl0 = lds32(bo + BL_OFF + 8 * RSB);
            uint32_t cl1 = lds32(bo + BL_OFF + 8 * RSB + 16);
            mma_bf16(c1, ah0, ah1, ah2, ah3, ch0, ch1);
            mma_bf16(c1, ah0, ah1, ah2, ah3, cl0, cl1);
            mma_bf16(c1, al0, al1, al2, al3, ch0, ch1);
        }
    }

    // epilogue: C[row=v][col=ch] ; c0/c1 thread map: rows g,g+8; cols 2tc,2tc+1
    {
        float* po = g_part[ks];
        const int v = vt * 128 + vw + g;
        const int cha = 2 * tc;
        const int chb = 8 + 2 * tc;
        po[(size_t)cha * V + v]           = c0[0];
        po[(size_t)(cha + 1) * V + v]     = c0[1];
        po[(size_t)cha * V + v + 8]       = c0[2];
        po[(size_t)(cha + 1) * V + v + 8] = c0[3];
        po[(size_t)chb * V + v]           = c1[0];
        po[(size_t)(chb + 1) * V + v]     = c1[1];
        po[(size_t)chb * V + v + 8]       = c1[2];
        po[(size_t)(chb + 1) * V + v + 8] = c1[3];
    }
}

// T_out = a * (sum of 3 partials) + b * prev   (elementwise over [CIN][V])
__global__ __launch_bounds__(256)
void cheb_reduce(const float* __restrict__ prev, float* __restrict__ Tout,
                 float a, float b)
{
    const int idx = blockIdx.x * 256 + threadIdx.x;
    float s = g_part[0][idx] + g_part[1][idx] + g_part[2][idx];
    float r = a * s;
    if (b != 0.0f) r += b * prev[idx];
    Tout[idx] = r;
}

// out[o][v] = bias[o] + sum_k sum_i T_k[i][v] * W[k][i][o]
__global__ __launch_bounds__(128)
void cheb_combine(const float* __restrict__ x,
                  const float* __restrict__ Wt,
                  const float* __restrict__ bias,
                  float* __restrict__ out)
{
    __shared__ float Ws[KORD * CIN * COUT];
    __shared__ float bs[COUT];
    const int tid = threadIdx.x;
    for (int idx = tid; idx < KORD * CIN * COUT; idx += blockDim.x) Ws[idx] = Wt[idx];
    if (tid < COUT) bs[tid] = bias[tid];
    __syncthreads();

    const int v = blockIdx.x * blockDim.x + tid;

    float acc[COUT];
#pragma unroll
    for (int o = 0; o < COUT; o++) acc[o] = bs[o];

#pragma unroll
    for (int k = 0; k < KORD; k++) {
        const float* T = (k == 0) ? x : &g_T[k - 1][0];
#pragma unroll
        for (int i = 0; i < CIN; i++) {
            float tv = T[(size_t)i * V + v];
            const float* wrow = &Ws[(k * CIN + i) * COUT];
#pragma unroll
            for (int o = 0; o < COUT; o++) acc[o] = fmaf(tv, wrow[o], acc[o]);
        }
    }
#pragma unroll
    for (int o = 0; o < COUT; o++) out[(size_t)o * V + v] = acc[o];
}

extern "C" void kernel_launch(void* const* d_in, const int* in_sizes, int n_in,
                              void* d_out, int out_size)
{
    const float* x  = (const float*)d_in[0];
    const float* L  = (const float*)d_in[1];
    const float* Wt = (const float*)d_in[2];
    const float* b  = (const float*)d_in[3];
    float* out = (float*)d_out;

    float* gT = nullptr;
    cudaGetSymbolAddress((void**)&gT, g_T);

    const dim3 pgrid(96 * NKS);   // 288 CTAs = one full wave at 2 CTAs/SM
    const dim3 pblk(256);
    const dim3 rgrid(CV / 256);

    float* T1 = gT + 0 * CV;
    float* T2 = gT + 1 * CV;
    float* T3 = gT + 2 * CV;
    float* T4 = gT + 3 * CV;

    // T1 = x @ L^T
    cheb_pass_mma<<<pgrid, pblk>>>(L, x);
    cheb_reduce<<<rgrid, 256>>>(x, T1, 1.0f, 0.0f);
    // T2 = 2 T1 @ L^T - x
    cheb_pass_mma<<<pgrid, pblk>>>(L, T1);
    cheb_reduce<<<rgrid, 256>>>(x, T2, 2.0f, -1.0f);
    // T3 = 2 T2 @ L^T - T1
    cheb_pass_mma<<<pgrid, pblk>>>(L, T2);
    cheb_reduce<<<rgrid, 256>>>(T1, T3, 2.0f, -1.0f);
    // T4 = 2 T3 @ L^T - T2
    cheb_pass_mma<<<pgrid, pblk>>>(L, T3);
    cheb_reduce<<<rgrid, 256>>>(T2, T4, 2.0f, -1.0f);
    // out = einsum + bias
    cheb_combine<<<V / 128, 128>>>(x, Wt, b, out);
}

// round 8
// speedup vs baseline: 2.5468x; 2.5468x over previous
#include <cuda_runtime.h>
#include <cstdint>

#define V 12288
#define CIN 16
#define COUT 32
#define KORD 5
#define NKS 3               // k-slices per pass  -> 96*3 = 288 CTAs = 1 wave @2/SM
#define KSL (V / NKS)       // 4096
#define CHK 64              // u per chunk
#define NCHK (KSL / CHK)    // 64
#define CV (CIN * V)
#define RS 72               // smem row stride in bf16 elements
#define RSB (RS * 2)        // 144 bytes

// fp32 scratch: T1..T4 and per-kslice partials
__device__ float g_T[4][CV];
__device__ float g_part[NKS][CV];

// per-stage smem byte offsets
#define AH_OFF 0
#define AL_OFF (128 * RSB)            // 18432
#define BH_OFF (2 * 128 * RSB)        // 36864
#define BL_OFF (BH_OFF + 16 * RSB)    // 39168
#define STAGE  (BL_OFF + 16 * RSB)    // 41472 per stage
#define SMEM_DYN (2 * STAGE)          // 82944

__device__ __forceinline__ uint32_t lds32(uint32_t a) {
    uint32_t v;
    asm volatile("ld.shared.b32 %0, [%1];" : "=r"(v) : "r"(a));
    return v;
}
__device__ __forceinline__ void sts64(uint32_t a, uint32_t w0, uint32_t w1) {
    asm volatile("st.shared.v2.b32 [%0], {%1,%2};" :: "r"(a), "r"(w0), "r"(w1) : "memory");
}

// split fp32 x4 -> bf16 hi (truncate) + bf16 lo (residual, RN); store 8B to each tile
__device__ __forceinline__ void split_sts(float4 f, uint32_t ah, uint32_t al) {
    uint32_t b0 = __float_as_uint(f.x), b1 = __float_as_uint(f.y);
    uint32_t b2 = __float_as_uint(f.z), b3 = __float_as_uint(f.w);
    uint32_t h0 = __byte_perm(b0, b1, 0x7632);
    uint32_t h1 = __byte_perm(b2, b3, 0x7632);
    float l0 = f.x - __uint_as_float(b0 & 0xFFFF0000u);
    float l1 = f.y - __uint_as_float(b1 & 0xFFFF0000u);
    float l2 = f.z - __uint_as_float(b2 & 0xFFFF0000u);
    float l3 = f.w - __uint_as_float(b3 & 0xFFFF0000u);
    uint32_t w0, w1;
    asm("cvt.rn.bf16x2.f32 %0, %1, %2;" : "=r"(w0) : "f"(l1), "f"(l0));
    asm("cvt.rn.bf16x2.f32 %0, %1, %2;" : "=r"(w1) : "f"(l3), "f"(l2));
    sts64(ah, h0, h1);
    sts64(al, w0, w1);
}

__device__ __forceinline__ void mma_bf16(float* c, uint32_t a0, uint32_t a1,
                                         uint32_t a2, uint32_t a3,
                                         uint32_t b0, uint32_t b1) {
    asm volatile("mma.sync.aligned.m16n8k16.row.col.f32.bf16.bf16.f32 "
                 "{%0,%1,%2,%3}, {%4,%5,%6,%7}, {%8,%9}, {%0,%1,%2,%3};"
                 : "+f"(c[0]), "+f"(c[1]), "+f"(c[2]), "+f"(c[3])
                 : "r"(a0), "r"(a1), "r"(a2), "r"(a3), "r"(b0), "r"(b1));
}

// ---------------- pass kernel ----------------
// g_part[ks][ch][v] = sum_{u in kslice} B[ch][u] * L[v][u]
// L fp32 [V][V]; B fp32 [CIN][V]. In-kernel bf16 hi/lo split, 3 HMMA products.
__global__ __launch_bounds__(256, 2)
void cheb_pass_mma(const float* __restrict__ L, const float* __restrict__ B)
{
    extern __shared__ __align__(16) uint8_t smem[];
    const uint32_t sb = (uint32_t)__cvta_generic_to_shared(smem);

    const int t    = threadIdx.x;
    const int warp = t >> 5;
    const int lane = t & 31;
    const int g    = lane >> 2;      // group id (0..7)
    const int tc   = lane & 3;       // thread in group
    const int vt   = blockIdx.x % 96;
    const int ks   = blockIdx.x / 96;
    const int ub   = ks * KSL;

    // Coalesced staging map: thread t, iter j -> row j*16 + (t>>4), col quad (t&15).
    // A warp LDG touches 2 rows x 256B = 4 lines (vs 32 before).
    const int rh = t >> 4;           // 0..15
    const int cq = t & 15;           // col quad
    const float* Ag = L + (size_t)(vt * 128 + rh) * V + ub + cq * 4;
    const float* Bg = B + (size_t)rh * V + ub + cq * 4;
    const uint32_t st_off = (uint32_t)(rh * RSB + cq * 8);   // smem offset (row rh, col 4cq)

    // fragment LDS offsets (per warp: rows vw..vw+15), relative to stage base
    const int vw = warp * 16;
    const uint32_t a_frag = (uint32_t)((vw + g) * RSB + tc * 4);
    const uint32_t b_frag = (uint32_t)(g * RSB + tc * 4);

    float c0[4] = {0.f, 0.f, 0.f, 0.f};   // channels 0..7
    float c1[4] = {0.f, 0.f, 0.f, 0.f};   // channels 8..15

    float4 la[8];
    float4 lb;

    // prologue: load+stage chunk 0, load chunk 1
#pragma unroll
    for (int j = 0; j < 8; j++)
        la[j] = __ldcs((const float4*)(Ag + (size_t)j * 16 * V));
    lb = __ldg((const float4*)(Bg));
    {
        const uint32_t s0 = sb;
#pragma unroll
        for (int j = 0; j < 8; j++)
            split_sts(la[j], s0 + AH_OFF + st_off + j * 2304,
                             s0 + AL_OFF + st_off + j * 2304);
        split_sts(lb, s0 + BH_OFF + st_off, s0 + BL_OFF + st_off);
    }
#pragma unroll
    for (int j = 0; j < 8; j++)
        la[j] = __ldcs((const float4*)(Ag + (size_t)j * 16 * V + CHK));
    lb = __ldg((const float4*)(Bg + CHK));
    __syncthreads();

#pragma unroll 1
    for (int c = 0; c < NCHK; c++) {
        const uint32_t sbuf = sb + (uint32_t)(c & 1) * STAGE;

        // stage chunk c+1 into the other buffer (regs loaded last iter)
        if (c + 1 < NCHK) {
            const uint32_t so = sb + (uint32_t)((c + 1) & 1) * STAGE;
#pragma unroll
            for (int j = 0; j < 8; j++)
                split_sts(la[j], so + AH_OFF + st_off + j * 2304,
                                 so + AL_OFF + st_off + j * 2304);
            split_sts(lb, so + BH_OFF + st_off, so + BL_OFF + st_off);
        }
        // prefetch chunk c+2
        if (c + 2 < NCHK) {
            const int off = (c + 2) * CHK;
#pragma unroll
            for (int j = 0; j < 8; j++)
                la[j] = __ldcs((const float4*)(Ag + (size_t)j * 16 * V + off));
            lb = __ldg((const float4*)(Bg + off));
        }

        // compute chunk c: 4 k-steps x (2 n-tiles x 3 products)
#pragma unroll
        for (int s = 0; s < 4; s++) {
            const uint32_t ao = sbuf + a_frag + s * 32;
            const uint32_t bo = sbuf + b_frag + s * 32;
            uint32_t ah0 = lds32(ao + AH_OFF);
            uint32_t ah1 = lds32(ao + AH_OFF + 8 * RSB);
            uint32_t ah2 = lds32(ao + AH_OFF + 16);
            uint32_t ah3 = lds32(ao + AH_OFF + 8 * RSB + 16);
            uint32_t al0 = lds32(ao + AL_OFF);
            uint32_t al1 = lds32(ao + AL_OFF + 8 * RSB);
            uint32_t al2 = lds32(ao + AL_OFF + 16);
            uint32_t al3 = lds32(ao + AL_OFF + 8 * RSB + 16);

            uint32_t bh0 = lds32(bo + BH_OFF);
            uint32_t bh1 = lds32(bo + BH_OFF + 16);
            uint32_t bl0 = lds32(bo + BL_OFF);
            uint32_t bl1 = lds32(bo + BL_OFF + 16);
            mma_bf16(c0, ah0, ah1, ah2, ah3, bh0, bh1);
            mma_bf16(c0, ah0, ah1, ah2, ah3, bl0, bl1);
            mma_bf16(c0, al0, al1, al2, al3, bh0, bh1);

            uint32_t ch0 = lds32(bo + BH_OFF + 8 * RSB);
            uint32_t ch1 = lds32(bo + BH_OFF + 8 * RSB + 16);
            uint32_t cl0 = lds32(bo + BL_OFF + 8 * RSB);
            uint32_t cl1 = lds32(bo + BL_OFF + 8 * RSB + 16);
            mma_bf16(c1, ah0, ah1, ah2, ah3, ch0, ch1);
            mma_bf16(c1, ah0, ah1, ah2, ah3, cl0, cl1);
            mma_bf16(c1, al0, al1, al2, al3, ch0, ch1);
        }
        __syncthreads();
    }

    // epilogue: C[row=v][col=ch] ; thread map: rows g,g+8; cols 2tc,2tc+1
    {
        float* po = g_part[ks];
        const int v = vt * 128 + vw + g;
        const int cha = 2 * tc;
        const int chb = 8 + 2 * tc;
        po[(size_t)cha * V + v]           = c0[0];
        po[(size_t)(cha + 1) * V + v]     = c0[1];
        po[(size_t)cha * V + v + 8]       = c0[2];
        po[(size_t)(cha + 1) * V + v + 8] = c0[3];
        po[(size_t)chb * V + v]           = c1[0];
        po[(size_t)(chb + 1) * V + v]     = c1[1];
        po[(size_t)chb * V + v + 8]       = c1[2];
        po[(size_t)(chb + 1) * V + v + 8] = c1[3];
    }
}

// T_out = a * (sum of 3 partials) + b * prev   (elementwise over [CIN][V])
__global__ __launch_bounds__(256)
void cheb_reduce(const float* __restrict__ prev, float* __restrict__ Tout,
                 float a, float b)
{
    const int idx = blockIdx.x * 256 + threadIdx.x;
    float s = g_part[0][idx] + g_part[1][idx] + g_part[2][idx];
    float r = a * s;
    if (b != 0.0f) r += b * prev[idx];
    Tout[idx] = r;
}

// out[o][v] = bias[o] + sum_k sum_i T_k[i][v] * W[k][i][o]
__global__ __launch_bounds__(128)
void cheb_combine(const float* __restrict__ x,
                  const float* __restrict__ Wt,
                  const float* __restrict__ bias,
                  float* __restrict__ out)
{
    __shared__ float Ws[KORD * CIN * COUT];
    __shared__ float bs[COUT];
    const int tid = threadIdx.x;
    for (int idx = tid; idx < KORD * CIN * COUT; idx += blockDim.x) Ws[idx] = Wt[idx];
    if (tid < COUT) bs[tid] = bias[tid];
    __syncthreads();

    const int v = blockIdx.x * blockDim.x + tid;

    float acc[COUT];
#pragma unroll
    for (int o = 0; o < COUT; o++) acc[o] = bs[o];

#pragma unroll
    for (int k = 0; k < KORD; k++) {
        const float* T = (k == 0) ? x : &g_T[k - 1][0];
#pragma unroll
        for (int i = 0; i < CIN; i++) {
            float tv = T[(size_t)i * V + v];
            const float* wrow = &Ws[(k * CIN + i) * COUT];
#pragma unroll
            for (int o = 0; o < COUT; o++) acc[o] = fmaf(tv, wrow[o], acc[o]);
        }
    }
#pragma unroll
    for (int o = 0; o < COUT; o++) out[(size_t)o * V + v] = acc[o];
}

extern "C" void kernel_launch(void* const* d_in, const int* in_sizes, int n_in,
                              void* d_out, int out_size)
{
    const float* x  = (const float*)d_in[0];
    const float* L  = (const float*)d_in[1];
    const float* Wt = (const float*)d_in[2];
    const float* b  = (const float*)d_in[3];
    float* out = (float*)d_out;

    float* gT = nullptr;
    cudaGetSymbolAddress((void**)&gT, g_T);

    cudaFuncSetAttribute(cheb_pass_mma, cudaFuncAttributeMaxDynamicSharedMemorySize,
                         SMEM_DYN);

    const dim3 pgrid(96 * NKS);   // 288 CTAs = one full wave at 2 CTAs/SM
    const dim3 pblk(256);
    const dim3 rgrid(CV / 256);

    float* T1 = gT + 0 * CV;
    float* T2 = gT + 1 * CV;
    float* T3 = gT + 2 * CV;
    float* T4 = gT + 3 * CV;

    // T1 = x @ L^T
    cheb_pass_mma<<<pgrid, pblk, SMEM_DYN>>>(L, x);
    cheb_reduce<<<rgrid, 256>>>(x, T1, 1.0f, 0.0f);
    // T2 = 2 T1 @ L^T - x
    cheb_pass_mma<<<pgrid, pblk, SMEM_DYN>>>(L, T1);
    cheb_reduce<<<rgrid, 256>>>(x, T2, 2.0f, -1.0f);
    // T3 = 2 T2 @ L^T - T1
    cheb_pass_mma<<<pgrid, pblk, SMEM_DYN>>>(L, T2);
    cheb_reduce<<<rgrid, 256>>>(T1, T3, 2.0f, -1.0f);
    // T4 = 2 T3 @ L^T - T2
    cheb_pass_mma<<<pgrid, pblk, SMEM_DYN>>>(L, T3);
    cheb_reduce<<<rgrid, 256>>>(T2, T4, 2.0f, -1.0f);
    // out = einsum + bias
    cheb_combine<<<V / 128, 128>>>(x, Wt, b, out);
}